// round 10
// baseline (speedup 1.0000x reference)
#include <cuda_runtime.h>
#include <cuda_fp16.h>
#include <cstdint>

#define MTOT 8192
#define KDIM 4096
#define NDIM 16384
#define BM 128
#define BN 128
#define BK 64
#define NSTAGE 3
#define NCHUNK (KDIM / BK)   // 64
#define NTHREADS 128

#define STAGE_BYTES 32768          // A 16KB + B 16KB
#define B_OFF 16384
#define SMEM_TOTAL (NSTAGE * STAGE_BYTES)   // 96KB -> 2 CTAs/SM

__device__ __half g_Wh[(size_t)NDIM * KDIM];  // 128 MB
__device__ __half g_Xh[(size_t)MTOT * KDIM];  // 64 MB

__device__ __forceinline__ uint32_t smem_u32(const void* p) {
    uint32_t a;
    asm("{ .reg .u64 t; cvta.to.shared.u64 t, %1; cvt.u32.u64 %0, t; }" : "=r"(a) : "l"(p));
    return a;
}
__device__ __forceinline__ void cp_async16(uint32_t dst, const void* src) {
    asm volatile("cp.async.cg.shared.global [%0], [%1], 16;" :: "r"(dst), "l"(src) : "memory");
}
__device__ __forceinline__ void cp_commit() {
    asm volatile("cp.async.commit_group;" ::: "memory");
}
template <int N>
__device__ __forceinline__ void cp_wait() {
    asm volatile("cp.async.wait_group %0;" :: "n"(N) : "memory");
}
__device__ __forceinline__ void ldsm_x4(uint32_t* r, uint32_t addr) {
    asm volatile("ldmatrix.sync.aligned.m8n8.x4.shared.b16 {%0,%1,%2,%3}, [%4];"
                 : "=r"(r[0]), "=r"(r[1]), "=r"(r[2]), "=r"(r[3]) : "r"(addr));
}
__device__ __forceinline__ void mma16816(float* c, const uint32_t* a, uint32_t b0, uint32_t b1) {
    asm volatile(
        "mma.sync.aligned.m16n8k16.row.col.f32.f16.f16.f32 "
        "{%0,%1,%2,%3}, {%4,%5,%6,%7}, {%8,%9}, {%0,%1,%2,%3};"
        : "+f"(c[0]), "+f"(c[1]), "+f"(c[2]), "+f"(c[3])
        : "r"(a[0]), "r"(a[1]), "r"(a[2]), "r"(a[3]), "r"(b0), "r"(b1));
}
__device__ __forceinline__ float gelu_tanh(float v) {
    float u = v * (1.0f + 0.044715f * v * v);
    float z = 1.5957691216057308f * u;
    return __fdividef(v, 1.0f + __expf(-z));
}

// ---------------------------------------------- fused converter (W then X)
#define WBLK ((NDIM * KDIM / 32) / 256)   // 8192 blocks
#define XBLK ((MTOT * KDIM / 16) / 256)   // 8192 blocks
__global__ void k_convert(const int4* __restrict__ w, const float4* __restrict__ x) {
    int b = blockIdx.x;
    if (b < WBLK) {
        int i = (b * 256 + threadIdx.x) * 8;   // 32 ints/thread
        __half2* o = reinterpret_cast<__half2*>(g_Wh);
#pragma unroll
        for (int u = 0; u < 8; ++u) {
            int4 v = w[i + u];
            o[2 * (i + u) + 0] = __floats2half2_rn((float)v.x, (float)v.y);
            o[2 * (i + u) + 1] = __floats2half2_rn((float)v.z, (float)v.w);
        }
    } else {
        int i = ((b - WBLK) * 256 + threadIdx.x) * 4;  // 16 floats/thread
        __half2* o = reinterpret_cast<__half2*>(g_Xh);
#pragma unroll
        for (int u = 0; u < 4; ++u) {
            float4 v = x[i + u];
            o[2 * (i + u) + 0] = __floats2half2_rn(v.x, v.y);
            o[2 * (i + u) + 1] = __floats2half2_rn(v.z, v.w);
        }
    }
}

// ----------------------------------------------------------- GEMM
__device__ __forceinline__ void load_stage(uint32_t sb, int stage, int m0, int n0,
                                           int kb, int tid) {
    uint32_t As = sb + stage * STAGE_BYTES;
    uint32_t Bs = As + B_OFF;
    const __half* ga = g_Xh + (size_t)m0 * KDIM + kb;
    const __half* gb = g_Wh + (size_t)n0 * KDIM + kb;
#pragma unroll
    for (int q = tid; q < 1024; q += NTHREADS) {
        int r = q >> 3, c = q & 7;
        uint32_t d = (uint32_t)r * 128 + (uint32_t)((c ^ (r & 7)) * 16);
        size_t go = (size_t)r * KDIM + c * 8;
        cp_async16(As + d, ga + go);
        cp_async16(Bs + d, gb + go);
    }
}

__global__ void __launch_bounds__(NTHREADS, 2)
k_gemm(const float* __restrict__ wscale, const float* __restrict__ bias,
       float* __restrict__ out) {
    extern __shared__ char smem[];
    const uint32_t sb = smem_u32(smem);
    const int tid = threadIdx.x;
    const int wid = tid >> 5;
    const int lid = tid & 31;
    const int warp_m = wid & 1;
    const int warp_n = wid >> 1;

    int pid = blockIdx.x;            // 8192 CTAs: 64 m x 128 n, 8-m groups
    int pid_m = (pid >> 10) * 8 + (pid & 7);
    int pid_n = (pid & 1023) >> 3;
    const int m0 = pid_m * BM;
    const int n0 = pid_n * BN;

    const uint32_t sw = (uint32_t)(lid & 7);
    const uint32_t rowA = warp_m * 64 + (lid & 7) + ((lid >> 3) & 1) * 8;
    const uint32_t cgA = (uint32_t)((lid >> 4) & 1);
    const uint32_t rowBb = warp_n * 64 + ((lid >> 4) & 1) * 8 + (lid & 7);
    const uint32_t cgB = (uint32_t)((lid >> 3) & 1);

    float acc[4][8][4];
#pragma unroll
    for (int a = 0; a < 4; ++a)
#pragma unroll
        for (int b = 0; b < 8; ++b)
#pragma unroll
            for (int c = 0; c < 4; ++c) acc[a][b][c] = 0.0f;

    load_stage(sb, 0, m0, n0, 0, tid);
    cp_commit();
    load_stage(sb, 1, m0, n0, BK, tid);
    cp_commit();

    int st = 0, st_next = 2;
    uint32_t a_cur[4][4], a_nxt[4][4];   // A double-buffer only (16 extra regs)

#pragma unroll 1
    for (int i = 0; i < NCHUNK; ++i) {
        cp_wait<NSTAGE - 2>();
        __syncthreads();
        if (i + 2 < NCHUNK)
            load_stage(sb, st_next, m0, n0, (i + 2) * BK, tid);
        cp_commit();

        const uint32_t As = sb + st * STAGE_BYTES;
        const uint32_t Bs = As + B_OFF;

        // prefetch A fragments for ks=0
#pragma unroll
        for (int mt = 0; mt < 4; ++mt)
            ldsm_x4(a_cur[mt], As + (rowA + mt * 16) * 128 + (cgA ^ sw) * 16);

#pragma unroll
        for (int ks = 0; ks < 4; ++ks) {
            uint32_t b_fr[4][4];
#pragma unroll
            for (int np = 0; np < 4; ++np)
                ldsm_x4(b_fr[np], Bs + (rowBb + np * 16) * 128
                               + (((uint32_t)ks * 2 + cgB) ^ sw) * 16);
            if (ks < 3) {  // prefetch next A while B is in flight / MMA issues
#pragma unroll
                for (int mt = 0; mt < 4; ++mt)
                    ldsm_x4(a_nxt[mt], As + (rowA + mt * 16) * 128
                                   + (((uint32_t)(ks + 1) * 2 + cgA) ^ sw) * 16);
            }
#pragma unroll
            for (int mt = 0; mt < 4; ++mt)
#pragma unroll
                for (int nt = 0; nt < 8; ++nt)
                    mma16816(acc[mt][nt], a_cur[mt],
                             b_fr[nt >> 1][(nt & 1) * 2],
                             b_fr[nt >> 1][(nt & 1) * 2 + 1]);
#pragma unroll
            for (int mt = 0; mt < 4; ++mt)
#pragma unroll
                for (int r = 0; r < 4; ++r)
                    a_cur[mt][r] = a_nxt[mt][r];
        }
        if (++st == NSTAGE) st = 0;
        if (++st_next == NSTAGE) st_next = 0;
    }
    cp_wait<0>();

    // epilogue: dequant + bias + tanh-GELU, fp32 out
#pragma unroll
    for (int mt = 0; mt < 4; ++mt) {
        int mrow = m0 + warp_m * 64 + mt * 16 + (lid >> 2);
        float* o0 = out + (size_t)mrow * NDIM;
        float* o1 = o0 + (size_t)8 * NDIM;
#pragma unroll
        for (int nt = 0; nt < 8; ++nt) {
            int n = n0 + warp_n * 64 + nt * 8 + (lid & 3) * 2;
            float2 sc = *reinterpret_cast<const float2*>(wscale + n);
            float2 bi = *reinterpret_cast<const float2*>(bias + n);
            float2 v0, v1;
            v0.x = gelu_tanh(fmaf(acc[mt][nt][0], sc.x, bi.x));
            v0.y = gelu_tanh(fmaf(acc[mt][nt][1], sc.y, bi.y));
            v1.x = gelu_tanh(fmaf(acc[mt][nt][2], sc.x, bi.x));
            v1.y = gelu_tanh(fmaf(acc[mt][nt][3], sc.y, bi.y));
            *reinterpret_cast<float2*>(o0 + n) = v0;
            *reinterpret_cast<float2*>(o1 + n) = v1;
        }
    }
}

extern "C" void kernel_launch(void* const* d_in, const int* in_sizes, int n_in,
                              void* d_out, int out_size) {
    const float* x  = (const float*)d_in[0];
    const int*   w  = (const int*)d_in[1];
    const float* ws = (const float*)d_in[2];
    const float* bs = (const float*)d_in[3];
    float* out = (float*)d_out;

    k_convert<<<WBLK + XBLK, 256>>>((const int4*)w, (const float4*)x);

    cudaFuncSetAttribute(k_gemm, cudaFuncAttributeMaxDynamicSharedMemorySize, SMEM_TOTAL);
    k_gemm<<<(MTOT / BM) * (NDIM / BN), NTHREADS, SMEM_TOTAL>>>(ws, bs, out);
}

// round 12
// speedup vs baseline: 1.0008x; 1.0008x over previous
#include <cuda_runtime.h>
#include <cuda_fp16.h>
#include <cstdint>

#define MTOT 8192
#define KDIM 4096
#define NDIM 16384
#define BM 128
#define BN 128
#define BK 64
#define NSTAGE 3
#define NCHUNK (KDIM / BK)   // 64
#define NTHREADS 128

#define STAGE_BYTES 32768          // A 16KB + B 16KB
#define B_OFF 16384
#define SMEM_TOTAL (NSTAGE * STAGE_BYTES)   // 96KB -> 2 CTAs/SM

__device__ __half g_Wh[(size_t)NDIM * KDIM];  // 128 MB
__device__ __half g_Xh[(size_t)MTOT * KDIM];  // 64 MB

__device__ __forceinline__ uint32_t smem_u32(const void* p) {
    uint32_t a;
    asm("{ .reg .u64 t; cvta.to.shared.u64 t, %1; cvt.u32.u64 %0, t; }" : "=r"(a) : "l"(p));
    return a;
}
__device__ __forceinline__ void cp_async16(uint32_t dst, const void* src) {
    asm volatile("cp.async.cg.shared.global [%0], [%1], 16;" :: "r"(dst), "l"(src) : "memory");
}
__device__ __forceinline__ void cp_commit() {
    asm volatile("cp.async.commit_group;" ::: "memory");
}
template <int N>
__device__ __forceinline__ void cp_wait() {
    asm volatile("cp.async.wait_group %0;" :: "n"(N) : "memory");
}
__device__ __forceinline__ void ldsm_x4(uint32_t* r, uint32_t addr) {
    asm volatile("ldmatrix.sync.aligned.m8n8.x4.shared.b16 {%0,%1,%2,%3}, [%4];"
                 : "=r"(r[0]), "=r"(r[1]), "=r"(r[2]), "=r"(r[3]) : "r"(addr));
}
__device__ __forceinline__ void mma16816(float* c, const uint32_t* a, uint32_t b0, uint32_t b1) {
    asm volatile(
        "mma.sync.aligned.m16n8k16.row.col.f32.f16.f16.f32 "
        "{%0,%1,%2,%3}, {%4,%5,%6,%7}, {%8,%9}, {%0,%1,%2,%3};"
        : "+f"(c[0]), "+f"(c[1]), "+f"(c[2]), "+f"(c[3])
        : "r"(a[0]), "r"(a[1]), "r"(a[2]), "r"(a[3]), "r"(b0), "r"(b1));
}
__device__ __forceinline__ void stcs2(float* p, float x, float y) {
    asm volatile("st.global.cs.v2.f32 [%0], {%1, %2};" :: "l"(p), "f"(x), "f"(y) : "memory");
}
__device__ __forceinline__ float gelu_tanh(float v) {
    float u = v * (1.0f + 0.044715f * v * v);
    float z = 1.5957691216057308f * u;
    return __fdividef(v, 1.0f + __expf(-z));
}

// ---------------------------------------------- fused converter (W then X)
#define WBLK ((NDIM * KDIM / 32) / 256)   // 8192 blocks
#define XBLK ((MTOT * KDIM / 16) / 256)   // 8192 blocks
__global__ void k_convert(const int4* __restrict__ w, const float4* __restrict__ x) {
    int b = blockIdx.x;
    if (b < WBLK) {
        int i = (b * 256 + threadIdx.x) * 8;   // 32 ints/thread
        __half2* o = reinterpret_cast<__half2*>(g_Wh);
#pragma unroll
        for (int u = 0; u < 8; ++u) {
            int4 v = w[i + u];
            o[2 * (i + u) + 0] = __floats2half2_rn((float)v.x, (float)v.y);
            o[2 * (i + u) + 1] = __floats2half2_rn((float)v.z, (float)v.w);
        }
    } else {
        int i = ((b - WBLK) * 256 + threadIdx.x) * 4;  // 16 floats/thread
        __half2* o = reinterpret_cast<__half2*>(g_Xh);
#pragma unroll
        for (int u = 0; u < 4; ++u) {
            float4 v = x[i + u];
            o[2 * (i + u) + 0] = __floats2half2_rn(v.x, v.y);
            o[2 * (i + u) + 1] = __floats2half2_rn(v.z, v.w);
        }
    }
}

// ----------------------------------------------------------- GEMM
__device__ __forceinline__ void load_stage(uint32_t sb, int stage, int m0, int n0,
                                           int kb, int tid) {
    uint32_t As = sb + stage * STAGE_BYTES;
    uint32_t Bs = As + B_OFF;
    const __half* ga = g_Xh + (size_t)m0 * KDIM + kb;
    const __half* gb = g_Wh + (size_t)n0 * KDIM + kb;
#pragma unroll
    for (int q = tid; q < 1024; q += NTHREADS) {
        int r = q >> 3, c = q & 7;
        uint32_t d = (uint32_t)r * 128 + (uint32_t)((c ^ (r & 7)) * 16);
        size_t go = (size_t)r * KDIM + c * 8;
        cp_async16(As + d, ga + go);
        cp_async16(Bs + d, gb + go);
    }
}

__global__ void __launch_bounds__(NTHREADS, 2)
k_gemm(const float* __restrict__ wscale, const float* __restrict__ bias,
       float* __restrict__ out) {
    extern __shared__ char smem[];
    const uint32_t sb = smem_u32(smem);
    const int tid = threadIdx.x;
    const int wid = tid >> 5;
    const int lid = tid & 31;
    const int warp_m = wid & 1;
    const int warp_n = wid >> 1;

    int pid = blockIdx.x;            // 8192 CTAs: 64 m x 128 n, 8-m groups
    int pid_m = (pid >> 10) * 8 + (pid & 7);
    int pid_n = (pid & 1023) >> 3;
    const int m0 = pid_m * BM;
    const int n0 = pid_n * BN;

    const uint32_t sw = (uint32_t)(lid & 7);
    const uint32_t rowA = warp_m * 64 + (lid & 7) + ((lid >> 3) & 1) * 8;
    const uint32_t cgA = (uint32_t)((lid >> 4) & 1);
    const uint32_t rowBb = warp_n * 64 + ((lid >> 4) & 1) * 8 + (lid & 7);
    const uint32_t cgB = (uint32_t)((lid >> 3) & 1);

    float acc[4][8][4];
#pragma unroll
    for (int a = 0; a < 4; ++a)
#pragma unroll
        for (int b = 0; b < 8; ++b)
#pragma unroll
            for (int c = 0; c < 4; ++c) acc[a][b][c] = 0.0f;

    load_stage(sb, 0, m0, n0, 0, tid);
    cp_commit();
    load_stage(sb, 1, m0, n0, BK, tid);
    cp_commit();

    int st = 0, st_next = 2;
#pragma unroll 1
    for (int i = 0; i < NCHUNK; ++i) {
        cp_wait<NSTAGE - 2>();
        __syncthreads();
        if (i + 2 < NCHUNK)
            load_stage(sb, st_next, m0, n0, (i + 2) * BK, tid);
        cp_commit();

        const uint32_t As = sb + st * STAGE_BYTES;
        const uint32_t Bs = As + B_OFF;
#pragma unroll
        for (int ks = 0; ks < 4; ++ks) {
            uint32_t a[4][4];
#pragma unroll
            for (int mt = 0; mt < 4; ++mt)
                ldsm_x4(a[mt], As + (rowA + mt * 16) * 128
                               + (((uint32_t)ks * 2 + cgA) ^ sw) * 16);
            uint32_t b[4][4];
#pragma unroll
            for (int np = 0; np < 4; ++np)
                ldsm_x4(b[np], Bs + (rowBb + np * 16) * 128
                               + (((uint32_t)ks * 2 + cgB) ^ sw) * 16);
#pragma unroll
            for (int mt = 0; mt < 4; ++mt)
#pragma unroll
                for (int nt = 0; nt < 8; ++nt)
                    mma16816(acc[mt][nt], a[mt],
                             b[nt >> 1][(nt & 1) * 2], b[nt >> 1][(nt & 1) * 2 + 1]);
        }
        if (++st == NSTAGE) st = 0;
        if (++st_next == NSTAGE) st_next = 0;
    }
    cp_wait<0>();

    // epilogue: dequant + bias + tanh-GELU, fp32 out (streaming stores)
#pragma unroll
    for (int mt = 0; mt < 4; ++mt) {
        int mrow = m0 + warp_m * 64 + mt * 16 + (lid >> 2);
        float* o0 = out + (size_t)mrow * NDIM;
        float* o1 = o0 + (size_t)8 * NDIM;
#pragma unroll
        for (int nt = 0; nt < 8; ++nt) {
            int n = n0 + warp_n * 64 + nt * 8 + (lid & 3) * 2;
            float2 sc = *reinterpret_cast<const float2*>(wscale + n);
            float2 bi = *reinterpret_cast<const float2*>(bias + n);
            stcs2(o0 + n, gelu_tanh(fmaf(acc[mt][nt][0], sc.x, bi.x)),
                          gelu_tanh(fmaf(acc[mt][nt][1], sc.y, bi.y)));
            stcs2(o1 + n, gelu_tanh(fmaf(acc[mt][nt][2], sc.x, bi.x)),
                          gelu_tanh(fmaf(acc[mt][nt][3], sc.y, bi.y)));
        }
    }
}

extern "C" void kernel_launch(void* const* d_in, const int* in_sizes, int n_in,
                              void* d_out, int out_size) {
    const float* x  = (const float*)d_in[0];
    const int*   w  = (const int*)d_in[1];
    const float* ws = (const float*)d_in[2];
    const float* bs = (const float*)d_in[3];
    float* out = (float*)d_out;

    k_convert<<<WBLK + XBLK, 256>>>((const int4*)w, (const float4*)x);

    cudaFuncSetAttribute(k_gemm, cudaFuncAttributeMaxDynamicSharedMemorySize, SMEM_TOTAL);
    k_gemm<<<(MTOT / BM) * (NDIM / BN), NTHREADS, SMEM_TOTAL>>>(ws, bs, out);
}

// round 13
// speedup vs baseline: 1.0435x; 1.0427x over previous
#include <cuda_runtime.h>
#include <cuda_fp16.h>
#include <cstdint>

#define MTOT 8192
#define KDIM 4096
#define NDIM 16384
#define BM 128
#define BN 128
#define BK 64
#define NSTAGE 3
#define NCHUNK (KDIM / BK)   // 64
#define NTHREADS 256

#define STAGE_BYTES 32768          // A 16KB + B 16KB
#define B_OFF 16384
#define SMEM_TOTAL (NSTAGE * STAGE_BYTES)   // 96KB -> 2 CTAs/SM

__device__ __half g_Wh[(size_t)NDIM * KDIM];  // 128 MB
__device__ __half g_Xh[(size_t)MTOT * KDIM];  // 64 MB

__device__ __forceinline__ uint32_t smem_u32(const void* p) {
    uint32_t a;
    asm("{ .reg .u64 t; cvta.to.shared.u64 t, %1; cvt.u32.u64 %0, t; }" : "=r"(a) : "l"(p));
    return a;
}
__device__ __forceinline__ void cp_async16(uint32_t dst, const void* src) {
    asm volatile("cp.async.cg.shared.global [%0], [%1], 16;" :: "r"(dst), "l"(src) : "memory");
}
__device__ __forceinline__ void cp_commit() {
    asm volatile("cp.async.commit_group;" ::: "memory");
}
template <int N>
__device__ __forceinline__ void cp_wait() {
    asm volatile("cp.async.wait_group %0;" :: "n"(N) : "memory");
}
__device__ __forceinline__ void ldsm_x4(uint32_t* r, uint32_t addr) {
    asm volatile("ldmatrix.sync.aligned.m8n8.x4.shared.b16 {%0,%1,%2,%3}, [%4];"
                 : "=r"(r[0]), "=r"(r[1]), "=r"(r[2]), "=r"(r[3]) : "r"(addr));
}
__device__ __forceinline__ void mma16816(float* c, const uint32_t* a, uint32_t b0, uint32_t b1) {
    asm volatile(
        "mma.sync.aligned.m16n8k16.row.col.f32.f16.f16.f32 "
        "{%0,%1,%2,%3}, {%4,%5,%6,%7}, {%8,%9}, {%0,%1,%2,%3};"
        : "+f"(c[0]), "+f"(c[1]), "+f"(c[2]), "+f"(c[3])
        : "r"(a[0]), "r"(a[1]), "r"(a[2]), "r"(a[3]), "r"(b0), "r"(b1));
}
__device__ __forceinline__ float gelu_tanh(float v) {
    float u = v * (1.0f + 0.044715f * v * v);
    float z = 1.5957691216057308f * u;
    return __fdividef(v, 1.0f + __expf(-z));
}

// ----------------------------------------------------------- converters (R8 style)
__global__ void k_convert_w(const int4* __restrict__ w, int n4) {
    int i = blockIdx.x * blockDim.x + threadIdx.x;
    if (i < n4) {
        int4 v = w[i];
        __half2* o = reinterpret_cast<__half2*>(g_Wh);
        o[2 * i + 0] = __floats2half2_rn((float)v.x, (float)v.y);
        o[2 * i + 1] = __floats2half2_rn((float)v.z, (float)v.w);
    }
}
__global__ void k_convert_x(const float4* __restrict__ x, int n4) {
    int i = blockIdx.x * blockDim.x + threadIdx.x;
    if (i < n4) {
        float4 v = x[i];
        __half2* o = reinterpret_cast<__half2*>(g_Xh);
        o[2 * i + 0] = __floats2half2_rn(v.x, v.y);
        o[2 * i + 1] = __floats2half2_rn(v.z, v.w);
    }
}

// ----------------------------------------------------------- GEMM
__device__ __forceinline__ void load_stage(uint32_t sb, int stage, int m0, int n0,
                                           int kb, int tid) {
    uint32_t As = sb + stage * STAGE_BYTES;
    uint32_t Bs = As + B_OFF;
    const __half* ga = g_Xh + (size_t)m0 * KDIM + kb;
    const __half* gb = g_Wh + (size_t)n0 * KDIM + kb;
#pragma unroll
    for (int q = tid; q < 1024; q += NTHREADS) {       // 128 rows x 8 segs
        int r = q >> 3, c = q & 7;
        uint32_t d = (uint32_t)r * 128 + (uint32_t)((c ^ (r & 7)) * 16);
        size_t go = (size_t)r * KDIM + c * 8;
        cp_async16(As + d, ga + go);
        cp_async16(Bs + d, gb + go);
    }
}

__global__ void __launch_bounds__(NTHREADS, 2)
k_gemm(const float* __restrict__ wscale, const float* __restrict__ bias,
       float* __restrict__ out) {
    extern __shared__ char smem[];
    const uint32_t sb = smem_u32(smem);
    const int tid = threadIdx.x;
    const int wid = tid >> 5;
    const int lid = tid & 31;
    const int warp_m = wid & 1;      // 2 rows of 64
    const int warp_n = wid >> 1;     // 4 cols of 32

    int pid = blockIdx.x;            // 8192 CTAs: 64 m x 128 n, 8-m groups
    int pid_m = (pid >> 10) * 8 + (pid & 7);
    int pid_n = (pid & 1023) >> 3;
    const int m0 = pid_m * BM;
    const int n0 = pid_n * BN;

    const uint32_t sw = (uint32_t)(lid & 7);
    const uint32_t rowA = warp_m * 64 + (lid & 7) + ((lid >> 3) & 1) * 8;
    const uint32_t cgA = (uint32_t)((lid >> 4) & 1);
    const uint32_t rowBb = warp_n * 32 + ((lid >> 4) & 1) * 8 + (lid & 7);
    const uint32_t cgB = (uint32_t)((lid >> 3) & 1);

    float acc[4][4][4];
#pragma unroll
    for (int a = 0; a < 4; ++a)
#pragma unroll
        for (int b = 0; b < 4; ++b)
#pragma unroll
            for (int c = 0; c < 4; ++c) acc[a][b][c] = 0.0f;

    load_stage(sb, 0, m0, n0, 0, tid);
    cp_commit();
    load_stage(sb, 1, m0, n0, BK, tid);
    cp_commit();

    int st = 0, st_next = 2;
#pragma unroll 1
    for (int i = 0; i < NCHUNK; ++i) {
        cp_wait<NSTAGE - 2>();
        __syncthreads();
        if (i + 2 < NCHUNK)
            load_stage(sb, st_next, m0, n0, (i + 2) * BK, tid);
        cp_commit();

        const uint32_t As = sb + st * STAGE_BYTES;
        const uint32_t Bs = As + B_OFF;
#pragma unroll
        for (int ks = 0; ks < 4; ++ks) {
            uint32_t a[4][4];
#pragma unroll
            for (int mt = 0; mt < 4; ++mt)
                ldsm_x4(a[mt], As + (rowA + mt * 16) * 128
                               + (((uint32_t)ks * 2 + cgA) ^ sw) * 16);
            uint32_t b[2][4];
#pragma unroll
            for (int np = 0; np < 2; ++np)
                ldsm_x4(b[np], Bs + (rowBb + np * 16) * 128
                               + (((uint32_t)ks * 2 + cgB) ^ sw) * 16);
#pragma unroll
            for (int mt = 0; mt < 4; ++mt)
#pragma unroll
                for (int nt = 0; nt < 4; ++nt)
                    mma16816(acc[mt][nt], a[mt],
                             b[nt >> 1][(nt & 1) * 2], b[nt >> 1][(nt & 1) * 2 + 1]);
        }
        if (++st == NSTAGE) st = 0;
        if (++st_next == NSTAGE) st_next = 0;
    }
    cp_wait<0>();

    // epilogue: dequant + bias + tanh-GELU, fp32 out
#pragma unroll
    for (int mt = 0; mt < 4; ++mt) {
        int mrow = m0 + warp_m * 64 + mt * 16 + (lid >> 2);
        float* o0 = out + (size_t)mrow * NDIM;
        float* o1 = o0 + (size_t)8 * NDIM;
#pragma unroll
        for (int nt = 0; nt < 4; ++nt) {
            int n = n0 + warp_n * 32 + nt * 8 + (lid & 3) * 2;
            float2 sc = *reinterpret_cast<const float2*>(wscale + n);
            float2 bi = *reinterpret_cast<const float2*>(bias + n);
            float2 v0, v1;
            v0.x = gelu_tanh(fmaf(acc[mt][nt][0], sc.x, bi.x));
            v0.y = gelu_tanh(fmaf(acc[mt][nt][1], sc.y, bi.y));
            v1.x = gelu_tanh(fmaf(acc[mt][nt][2], sc.x, bi.x));
            v1.y = gelu_tanh(fmaf(acc[mt][nt][3], sc.y, bi.y));
            *reinterpret_cast<float2*>(o0 + n) = v0;
            *reinterpret_cast<float2*>(o1 + n) = v1;
        }
    }
}

extern "C" void kernel_launch(void* const* d_in, const int* in_sizes, int n_in,
                              void* d_out, int out_size) {
    const float* x  = (const float*)d_in[0];
    const int*   w  = (const int*)d_in[1];
    const float* ws = (const float*)d_in[2];
    const float* bs = (const float*)d_in[3];
    float* out = (float*)d_out;

    int w4 = NDIM * (KDIM / 4);
    int x4 = MTOT * (KDIM / 4);
    k_convert_w<<<w4 / 256, 256>>>((const int4*)w, w4);
    k_convert_x<<<x4 / 256, 256>>>((const float4*)x, x4);

    cudaFuncSetAttribute(k_gemm, cudaFuncAttributeMaxDynamicSharedMemorySize, SMEM_TOTAL);
    k_gemm<<<(MTOT / BM) * (NDIM / BN), NTHREADS, SMEM_TOTAL>>>(ws, bs, out);
}

// round 14
// speedup vs baseline: 1.1348x; 1.0874x over previous
#include <cuda_runtime.h>
#include <cuda_fp16.h>
#include <cstdint>

#define MTOT 8192
#define KDIM 4096
#define NDIM 16384
#define BM 128
#define BN 128
#define BK 64
#define NSTAGE 3
#define NCHUNK (KDIM / BK)   // 64
#define NTHREADS 128

#define STAGE_BYTES 32768          // A 16KB + B 16KB
#define B_OFF 16384
#define SMEM_TOTAL (NSTAGE * STAGE_BYTES)   // 96KB -> 2 CTAs/SM

__device__ __half g_Wh[(size_t)NDIM * KDIM];  // 128 MB
__device__ __half g_Xh[(size_t)MTOT * KDIM];  // 64 MB

__device__ __forceinline__ uint32_t smem_u32(const void* p) {
    uint32_t a;
    asm("{ .reg .u64 t; cvta.to.shared.u64 t, %1; cvt.u32.u64 %0, t; }" : "=r"(a) : "l"(p));
    return a;
}
__device__ __forceinline__ void cp_async16(uint32_t dst, const void* src) {
    asm volatile("cp.async.cg.shared.global [%0], [%1], 16;" :: "r"(dst), "l"(src) : "memory");
}
__device__ __forceinline__ void cp_commit() {
    asm volatile("cp.async.commit_group;" ::: "memory");
}
template <int N>
__device__ __forceinline__ void cp_wait() {
    asm volatile("cp.async.wait_group %0;" :: "n"(N) : "memory");
}
__device__ __forceinline__ void ldsm_x4(uint32_t* r, uint32_t addr) {
    asm volatile("ldmatrix.sync.aligned.m8n8.x4.shared.b16 {%0,%1,%2,%3}, [%4];"
                 : "=r"(r[0]), "=r"(r[1]), "=r"(r[2]), "=r"(r[3]) : "r"(addr));
}
__device__ __forceinline__ void mma16816(float* c, const uint32_t* a, uint32_t b0, uint32_t b1) {
    asm volatile(
        "mma.sync.aligned.m16n8k16.row.col.f32.f16.f16.f32 "
        "{%0,%1,%2,%3}, {%4,%5,%6,%7}, {%8,%9}, {%0,%1,%2,%3};"
        : "+f"(c[0]), "+f"(c[1]), "+f"(c[2]), "+f"(c[3])
        : "r"(a[0]), "r"(a[1]), "r"(a[2]), "r"(a[3]), "r"(b0), "r"(b1));
}
__device__ __forceinline__ float gelu_tanh(float v) {
    float u = v * (1.0f + 0.044715f * v * v);
    float z = 1.5957691216057308f * u;
    return __fdividef(v, 1.0f + __expf(-z));
}

// ----------------------------------------------------------- converters (coalesced)
__global__ void k_convert_w(const int4* __restrict__ w, int n4) {
    int i = blockIdx.x * blockDim.x + threadIdx.x;
    if (i < n4) {
        int4 v = w[i];
        __half2* o = reinterpret_cast<__half2*>(g_Wh);
        o[2 * i + 0] = __floats2half2_rn((float)v.x, (float)v.y);
        o[2 * i + 1] = __floats2half2_rn((float)v.z, (float)v.w);
    }
}
__global__ void k_convert_x(const float4* __restrict__ x, int n4) {
    int i = blockIdx.x * blockDim.x + threadIdx.x;
    if (i < n4) {
        float4 v = x[i];
        __half2* o = reinterpret_cast<__half2*>(g_Xh);
        o[2 * i + 0] = __floats2half2_rn(v.x, v.y);
        o[2 * i + 1] = __floats2half2_rn(v.z, v.w);
    }
}

// ----------------------------------------------------------- GEMM
__device__ __forceinline__ void load_stage(uint32_t sb, int stage, int m0, int n0,
                                           int kb, int tid) {
    uint32_t As = sb + stage * STAGE_BYTES;
    uint32_t Bs = As + B_OFF;
    const __half* ga = g_Xh + (size_t)m0 * KDIM + kb;
    const __half* gb = g_Wh + (size_t)n0 * KDIM + kb;
#pragma unroll
    for (int q = tid; q < 1024; q += NTHREADS) {
        int r = q >> 3, c = q & 7;
        uint32_t d = (uint32_t)r * 128 + (uint32_t)((c ^ (r & 7)) * 16);
        size_t go = (size_t)r * KDIM + c * 8;
        cp_async16(As + d, ga + go);
        cp_async16(Bs + d, gb + go);
    }
}

__global__ void __launch_bounds__(NTHREADS, 2)
k_gemm(const float* __restrict__ wscale, const float* __restrict__ bias,
       float* __restrict__ out) {
    extern __shared__ char smem[];
    const uint32_t sb = smem_u32(smem);
    const int tid = threadIdx.x;
    const int wid = tid >> 5;
    const int lid = tid & 31;
    const int warp_m = wid & 1;
    const int warp_n = wid >> 1;

    int pid = blockIdx.x;            // 8192 CTAs: 64 m x 128 n, 8-m groups
    int pid_m = (pid >> 10) * 8 + (pid & 7);
    int pid_n = (pid & 1023) >> 3;
    const int m0 = pid_m * BM;
    const int n0 = pid_n * BN;

    const uint32_t sw = (uint32_t)(lid & 7);
    const uint32_t rowA = warp_m * 64 + (lid & 7) + ((lid >> 3) & 1) * 8;
    const uint32_t cgA = (uint32_t)((lid >> 4) & 1);
    const uint32_t rowBb = warp_n * 64 + ((lid >> 4) & 1) * 8 + (lid & 7);
    const uint32_t cgB = (uint32_t)((lid >> 3) & 1);

    float acc[4][8][4];
#pragma unroll
    for (int a = 0; a < 4; ++a)
#pragma unroll
        for (int b = 0; b < 8; ++b)
#pragma unroll
            for (int c = 0; c < 4; ++c) acc[a][b][c] = 0.0f;

    load_stage(sb, 0, m0, n0, 0, tid);
    cp_commit();
    load_stage(sb, 1, m0, n0, BK, tid);
    cp_commit();

    int st = 0, st_next = 2;
    uint32_t a_fr[2][4][4], b_fr[2][4][4];

#pragma unroll 1
    for (int i = 0; i < NCHUNK; ++i) {
        cp_wait<NSTAGE - 2>();
        __syncthreads();

        const uint32_t As = sb + st * STAGE_BYTES;
        const uint32_t Bs = As + B_OFF;

        // prefetch ks=0 fragments
#pragma unroll
        for (int mt = 0; mt < 4; ++mt)
            ldsm_x4(a_fr[0][mt], As + (rowA + mt * 16) * 128 + (cgA ^ sw) * 16);
#pragma unroll
        for (int np = 0; np < 4; ++np)
            ldsm_x4(b_fr[0][np], Bs + (rowBb + np * 16) * 128 + (cgB ^ sw) * 16);

#pragma unroll
        for (int ks = 0; ks < 4; ++ks) {
            const int cur = ks & 1, nxt = cur ^ 1;
            if (ks < 3) {   // prefetch next k-step fragments
#pragma unroll
                for (int mt = 0; mt < 4; ++mt)
                    ldsm_x4(a_fr[nxt][mt], As + (rowA + mt * 16) * 128
                                   + (((uint32_t)(ks + 1) * 2 + cgA) ^ sw) * 16);
#pragma unroll
                for (int np = 0; np < 4; ++np)
                    ldsm_x4(b_fr[nxt][np], Bs + (rowBb + np * 16) * 128
                                   + (((uint32_t)(ks + 1) * 2 + cgB) ^ sw) * 16);
            }
#pragma unroll
            for (int mt = 0; mt < 4; ++mt)
#pragma unroll
                for (int nt = 0; nt < 8; ++nt)
                    mma16816(acc[mt][nt], a_fr[cur][mt],
                             b_fr[cur][nt >> 1][(nt & 1) * 2],
                             b_fr[cur][nt >> 1][(nt & 1) * 2 + 1]);
            if (ks == 0) {  // mid-chunk: issue next stage fill while tensor drains
                if (i + 2 < NCHUNK)
                    load_stage(sb, st_next, m0, n0, (i + 2) * BK, tid);
                cp_commit();
            }
        }
        if (++st == NSTAGE) st = 0;
        if (++st_next == NSTAGE) st_next = 0;
    }
    cp_wait<0>();

    // epilogue: dequant + bias + tanh-GELU, fp32 out
#pragma unroll
    for (int mt = 0; mt < 4; ++mt) {
        int mrow = m0 + warp_m * 64 + mt * 16 + (lid >> 2);
        float* o0 = out + (size_t)mrow * NDIM;
        float* o1 = o0 + (size_t)8 * NDIM;
#pragma unroll
        for (int nt = 0; nt < 8; ++nt) {
            int n = n0 + warp_n * 64 + nt * 8 + (lid & 3) * 2;
            float2 sc = *reinterpret_cast<const float2*>(wscale + n);
            float2 bi = *reinterpret_cast<const float2*>(bias + n);
            float2 v0, v1;
            v0.x = gelu_tanh(fmaf(acc[mt][nt][0], sc.x, bi.x));
            v0.y = gelu_tanh(fmaf(acc[mt][nt][1], sc.y, bi.y));
            v1.x = gelu_tanh(fmaf(acc[mt][nt][2], sc.x, bi.x));
            v1.y = gelu_tanh(fmaf(acc[mt][nt][3], sc.y, bi.y));
            *reinterpret_cast<float2*>(o0 + n) = v0;
            *reinterpret_cast<float2*>(o1 + n) = v1;
        }
    }
}

extern "C" void kernel_launch(void* const* d_in, const int* in_sizes, int n_in,
                              void* d_out, int out_size) {
    const float* x  = (const float*)d_in[0];
    const int*   w  = (const int*)d_in[1];
    const float* ws = (const float*)d_in[2];
    const float* bs = (const float*)d_in[3];
    float* out = (float*)d_out;

    int w4 = NDIM * (KDIM / 4);
    int x4 = MTOT * (KDIM / 4);
    k_convert_w<<<w4 / 256, 256>>>((const int4*)w, w4);
    k_convert_x<<<x4 / 256, 256>>>((const float4*)x, x4);

    cudaFuncSetAttribute(k_gemm, cudaFuncAttributeMaxDynamicSharedMemorySize, SMEM_TOTAL);
    k_gemm<<<(MTOT / BM) * (NDIM / BN), NTHREADS, SMEM_TOTAL>>>(ws, bs, out);
}